// round 10
// baseline (speedup 1.0000x reference)
#include <cuda_runtime.h>
#include <math.h>

// ---------------- problem constants ----------------
#define Bb    2
#define Ll    2048
#define Dd    1024
#define DIi   2048
#define Nn    16
#define DCV   4
#define DTRk  64
#define Iff   4096
#define Mm    (Bb*Ll)          // 4096 tokens
#define XPJ   (DTRk + 2*Nn)    // 96
#define XZW   (2*DIi)          // 4096
#define EPSf  1e-5f

// ---------------- scratch (device globals; aliased across phases) ----------------
// g_xz : xz (inproj out)          -> later reused as gate pre-activation (M x I)
// g_xc : conv+silu x, f/r         -> later reused as up (M x I)
// g_dt : softplus(dt), f/r        -> later reused as ysum (M x DI)
// g_yg : gated scan output, f/r
__device__ float g_res1[(size_t)Mm*Dd];
__device__ float g_h1  [(size_t)Mm*Dd];
__device__ float g_mout[(size_t)Mm*Dd];
__device__ float g_h2  [(size_t)Mm*Dd];
__device__ float g_xz  [(size_t)Mm*XZW];
__device__ float g_xc  [2][(size_t)Mm*DIi];
__device__ float g_dt  [2][(size_t)Mm*DIi];
__device__ float g_yg  [2][(size_t)Mm*DIi];
__device__ float g_xdbl[2][(size_t)Mm*XPJ];

// ---------------- fused add + LayerNorm (row = token, D = 1024) ----------------
__global__ void add_ln_kernel(const float* __restrict__ a, const float* __restrict__ b,
                              const float* __restrict__ w, const float* __restrict__ bias,
                              float* __restrict__ sum_out, float* __restrict__ ln_out)
{
    const int row = blockIdx.x;
    const int tid = threadIdx.x;                  // 256 threads, 4 elems each
    const size_t base = (size_t)row * Dd;
    float4 va = ((const float4*)(a + base))[tid];
    float4 vb = ((const float4*)(b + base))[tid];
    float4 v  = make_float4(va.x+vb.x, va.y+vb.y, va.z+vb.z, va.w+vb.w);

    float s  = v.x + v.y + v.z + v.w;
    float sq = v.x*v.x + v.y*v.y + v.z*v.z + v.w*v.w;
    #pragma unroll
    for (int o = 16; o > 0; o >>= 1) {
        s  += __shfl_xor_sync(0xffffffffu, s,  o);
        sq += __shfl_xor_sync(0xffffffffu, sq, o);
    }
    __shared__ float ssum[8], ssq[8];
    const int wid = tid >> 5, lane = tid & 31;
    if (lane == 0) { ssum[wid] = s; ssq[wid] = sq; }
    __syncthreads();
    if (tid == 0) {
        float S = 0.f, Q = 0.f;
        #pragma unroll
        for (int i = 0; i < 8; ++i) { S += ssum[i]; Q += ssq[i]; }
        float mean = S * (1.0f/Dd);
        float var  = Q * (1.0f/Dd) - mean*mean;
        ssum[0] = mean;
        ssq[0]  = rsqrtf(var + EPSf);
    }
    __syncthreads();
    const float mean = ssum[0], rstd = ssq[0];

    if (sum_out) ((float4*)(sum_out + base))[tid] = v;
    float4 w4 = ((const float4*)w)[tid];
    float4 b4 = ((const float4*)bias)[tid];
    float4 o;
    o.x = (v.x - mean) * rstd * w4.x + b4.x;
    o.y = (v.y - mean) * rstd * w4.y + b4.y;
    o.z = (v.z - mean) * rstd * w4.z + b4.z;
    o.w = (v.w - mean) * rstd * w4.w + b4.w;
    ((float4*)(ln_out + base))[tid] = o;
}

// ---------------- SGEMM  C[m,n] = sum_k A[m*lda+k] * B[n*ldb+k]  (NT) ----------------
// 128x128 tile, BK=8, 256 threads, 8x8 per-thread microtile. Requires K % 8 == 0,
// 16B-aligned rows (all our lda/ldb/ldc are multiples of 4 floats).
__global__ __launch_bounds__(256, 2)
void sgemm_nt(const float* __restrict__ A, const float* __restrict__ Bm,
              float* __restrict__ C, int M, int N, int K,
              int lda, int ldb, int ldc)
{
    __shared__ __align__(16) float As[8][128];
    __shared__ __align__(16) float Bs[8][128];
    const int bm = blockIdx.y * 128;
    const int bn = blockIdx.x * 128;
    const int tid  = threadIdx.x;
    const int tx   = tid & 15;        // n-tile
    const int ty   = tid >> 4;        // m-tile
    const int lrow = tid >> 1;        // 0..127
    const int lcol = (tid & 1) << 2;  // 0 or 4

    float acc[8][8];
    #pragma unroll
    for (int i = 0; i < 8; ++i)
        #pragma unroll
        for (int j = 0; j < 8; ++j) acc[i][j] = 0.f;

    const bool aval = (bm + lrow) < M;
    const bool bval = (bn + lrow) < N;
    const float* Aptr = A  + (size_t)(bm + lrow) * lda + lcol;
    const float* Bptr = Bm + (size_t)(bn + lrow) * ldb + lcol;

    for (int k0 = 0; k0 < K; k0 += 8) {
        float4 va = aval ? *(const float4*)(Aptr + k0) : make_float4(0,0,0,0);
        float4 vb = bval ? *(const float4*)(Bptr + k0) : make_float4(0,0,0,0);
        As[lcol+0][lrow] = va.x; As[lcol+1][lrow] = va.y;
        As[lcol+2][lrow] = va.z; As[lcol+3][lrow] = va.w;
        Bs[lcol+0][lrow] = vb.x; Bs[lcol+1][lrow] = vb.y;
        Bs[lcol+2][lrow] = vb.z; Bs[lcol+3][lrow] = vb.w;
        __syncthreads();
        #pragma unroll
        for (int kk = 0; kk < 8; ++kk) {
            float ra[8], rb[8];
            *(float4*)&ra[0] = *(const float4*)&As[kk][ty*8];
            *(float4*)&ra[4] = *(const float4*)&As[kk][ty*8+4];
            *(float4*)&rb[0] = *(const float4*)&Bs[kk][tx*8];
            *(float4*)&rb[4] = *(const float4*)&Bs[kk][tx*8+4];
            #pragma unroll
            for (int i = 0; i < 8; ++i)
                #pragma unroll
                for (int j = 0; j < 8; ++j)
                    acc[i][j] = fmaf(ra[i], rb[j], acc[i][j]);
        }
        __syncthreads();
    }

    #pragma unroll
    for (int i = 0; i < 8; ++i) {
        const int gm = bm + ty*8 + i;
        if (gm >= M) continue;
        float* crow = C + (size_t)gm * ldc;
        const int gn0 = bn + tx*8;
        if (gn0 + 7 < N) {
            *(float4*)(crow + gn0)     = *(float4*)&acc[i][0];
            *(float4*)(crow + gn0 + 4) = *(float4*)&acc[i][4];
        } else {
            #pragma unroll
            for (int j = 0; j < 8; ++j)
                if (gn0 + j < N) crow[gn0 + j] = acc[i][j];
        }
    }
}

// ---------------- depthwise causal conv (k=4) + SiLU, both directions ----------------
// Reverse direction is stored in reversed-l ("l'") domain: xr[b,l',d] uses orig index L-1-(l'-3+k).
__global__ void conv_silu_kernel(const float* __restrict__ wf, const float* __restrict__ bf,
                                 const float* __restrict__ wr, const float* __restrict__ br)
{
    const int idx = blockIdx.x * blockDim.x + threadIdx.x;
    if (idx >= Mm * DIi) return;
    const int dir = blockIdx.y;
    const int d = idx % DIi;
    const int t = idx / DIi;
    const int b = t / Ll, l = t % Ll;
    const float* w  = dir ? wr : wf;
    const float* bi = dir ? br : bf;
    float acc = bi[d];
    #pragma unroll
    for (int k = 0; k < DCV; ++k) {
        const int lk = l - (DCV-1) + k;
        if (lk >= 0) {
            const int lsrc = dir ? (Ll - 1 - lk) : lk;
            acc = fmaf(g_xz[((size_t)b*Ll + lsrc) * XZW + d], w[d*DCV + k], acc);
        }
    }
    g_xc[dir][idx] = acc / (1.f + __expf(-acc));   // SiLU
}

// ---------------- softplus(dt_lin + dtproj_b), in place ----------------
__global__ void softplus_kernel(const float* __restrict__ bf, const float* __restrict__ br)
{
    const size_t idx = (size_t)blockIdx.x * blockDim.x + threadIdx.x;
    if (idx >= (size_t)Mm * DIi) return;
    const int dir = blockIdx.y;
    const int d = (int)(idx % DIi);
    const float x = g_dt[dir][idx] + (dir ? br[d] : bf[d]);
    g_dt[dir][idx] = (x > 20.f) ? x : log1pf(__expf(x));
}

// ---------------- selective-state scan: thread per (b,d,n), 16-lane reduce ----------------
__global__ void scan_kernel(const float* __restrict__ alog_f, const float* __restrict__ dp_f,
                            const float* __restrict__ alog_r, const float* __restrict__ dp_r)
{
    const int dir = blockIdx.z;
    const int b   = blockIdx.y;
    const int d   = blockIdx.x * 32 + (threadIdx.x >> 4);
    const int n   = threadIdx.x & 15;

    const float* alog = dir ? alog_r : alog_f;
    const float* dp   = dir ? dp_r   : dp_f;
    const float A  = -expf(alog[d * Nn + n]);
    const float Dv = dp[d];
    const float* dt = g_dt[dir];
    const float* xc = g_xc[dir];
    const float* xd = g_xdbl[dir];
    float* yg = g_yg[dir];

    float s = 0.f;
    for (int l = 0; l < Ll; ++l) {
        const size_t t = (size_t)b * Ll + l;
        const float dtv = dt[t * DIi + d];
        const float xv  = xc[t * DIi + d];
        const float Bn  = xd[t * XPJ + DTRk + n];
        const float Cn  = xd[t * XPJ + DTRk + Nn + n];
        const float dA  = __expf(dtv * A);
        s = fmaf(s, dA, dtv * xv * Bn);
        float p = s * Cn;
        p += __shfl_xor_sync(0xffffffffu, p, 8);
        p += __shfl_xor_sync(0xffffffffu, p, 4);
        p += __shfl_xor_sync(0xffffffffu, p, 2);
        p += __shfl_xor_sync(0xffffffffu, p, 1);
        if (n == 0) {
            float y = p + xv * Dv;
            const int lz = dir ? (Ll - 1 - l) : l;                 // z in original order
            const float zv = g_xz[((size_t)b*Ll + lz) * XZW + DIi + d];
            y *= zv / (1.f + __expf(-zv));                          // * silu(z)
            yg[t * DIi + d] = y;
        }
    }
}

// ---------------- ysum[b,l,d] = yg_f[b,l,d] + yg_r[b,L-1-l,d]  (into g_dt[0]) ----------------
__global__ void combine_kernel()
{
    const size_t idx = (size_t)blockIdx.x * blockDim.x + threadIdx.x;
    if (idx >= (size_t)Mm * DIi) return;
    const int d = (int)(idx % DIi);
    const int t = (int)(idx / DIi);
    const int b = t / Ll, l = t % Ll;
    ((float*)g_dt)[idx] = g_yg[0][idx] + g_yg[1][((size_t)b*Ll + (Ll-1-l)) * DIi + d];
}

// ---------------- up = silu(gate) * up  (gate in g_xz, up in g_xc, flat M*I) ----------------
__global__ void silumul_kernel()
{
    const size_t idx = (size_t)blockIdx.x * blockDim.x + threadIdx.x;
    if (idx >= (size_t)Mm * Iff) return;
    const float g = g_xz[idx];
    ((float*)g_xc)[idx] = ((float*)g_xc)[idx] * g / (1.f + __expf(-g));
}

// ---------------- host ----------------
extern "C" void kernel_launch(void* const* d_in, const int* in_sizes, int n_in,
                              void* d_out, int out_size)
{
    const float* hs       = (const float*)d_in[0];
    const float* res      = (const float*)d_in[1];
    const float* inproj_w = (const float*)d_in[2];
    const float* outproj_w= (const float*)d_in[3];
    const float* conv_w_f = (const float*)d_in[4];
    const float* conv_b_f = (const float*)d_in[5];
    const float* xproj_w_f= (const float*)d_in[6];
    const float* dtproj_wf= (const float*)d_in[7];
    const float* dtproj_bf= (const float*)d_in[8];
    const float* alog_f   = (const float*)d_in[9];
    const float* dp_f     = (const float*)d_in[10];
    const float* conv_w_r = (const float*)d_in[11];
    const float* conv_b_r = (const float*)d_in[12];
    const float* xproj_w_r= (const float*)d_in[13];
    const float* dtproj_wr= (const float*)d_in[14];
    const float* dtproj_br= (const float*)d_in[15];
    const float* alog_r   = (const float*)d_in[16];
    const float* dp_r     = (const float*)d_in[17];
    const float* ln1w = (const float*)d_in[18];
    const float* ln1b = (const float*)d_in[19];
    const float* ln2w = (const float*)d_in[20];
    const float* ln2b = (const float*)d_in[21];
    const float* gate_w = (const float*)d_in[22];
    const float* up_w   = (const float*)d_in[23];
    const float* down_w = (const float*)d_in[24];

    float* out = (float*)d_out;
    float* res2_out = (out_size >= 2 * Mm * Dd) ? (out + (size_t)Mm * Dd) : nullptr;

    float *p_res1, *p_h1, *p_mout, *p_h2, *p_xz, *p_xc, *p_dt, *p_xdbl;
    cudaGetSymbolAddress((void**)&p_res1, g_res1);
    cudaGetSymbolAddress((void**)&p_h1,   g_h1);
    cudaGetSymbolAddress((void**)&p_mout, g_mout);
    cudaGetSymbolAddress((void**)&p_h2,   g_h2);
    cudaGetSymbolAddress((void**)&p_xz,   g_xz);
    cudaGetSymbolAddress((void**)&p_xc,   g_xc);
    cudaGetSymbolAddress((void**)&p_dt,   g_dt);
    cudaGetSymbolAddress((void**)&p_xdbl, g_xdbl);
    float* p_xcf   = p_xc;
    float* p_xcr   = p_xc + (size_t)Mm * DIi;
    float* p_dtf   = p_dt;
    float* p_dtr   = p_dt + (size_t)Mm * DIi;
    float* p_xdblf = p_xdbl;
    float* p_xdblr = p_xdbl + (size_t)Mm * XPJ;

    // 1) res1 = hs + residual; h1 = LN1(res1)
    add_ln_kernel<<<Mm, 256>>>(hs, res, ln1w, ln1b, p_res1, p_h1);

    // 2) xz = h1 @ inproj_w^T     (4096 x 4096 x 1024)
    sgemm_nt<<<dim3(XZW/128, Mm/128), 256>>>(p_h1, inproj_w, p_xz, Mm, XZW, Dd, Dd, Dd, XZW);

    // 3) conv + silu (both directions; reverse stored in reversed-l domain)
    conv_silu_kernel<<<dim3((Mm*DIi)/256, 2), 256>>>(conv_w_f, conv_b_f, conv_w_r, conv_b_r);

    // 4) x_dbl = x @ xproj_w^T    (4096 x 96 x 2048) per dir
    sgemm_nt<<<dim3(1, Mm/128), 256>>>(p_xcf, xproj_w_f, p_xdblf, Mm, XPJ, DIi, DIi, DIi, XPJ);
    sgemm_nt<<<dim3(1, Mm/128), 256>>>(p_xcr, xproj_w_r, p_xdblr, Mm, XPJ, DIi, DIi, DIi, XPJ);

    // 5) dt_lin = dt_part @ dtproj_w^T   (4096 x 2048 x 64) per dir  (dt_part = first 64 cols of x_dbl)
    sgemm_nt<<<dim3(DIi/128, Mm/128), 256>>>(p_xdblf, dtproj_wf, p_dtf, Mm, DIi, DTRk, XPJ, DTRk, DIi);
    sgemm_nt<<<dim3(DIi/128, Mm/128), 256>>>(p_xdblr, dtproj_wr, p_dtr, Mm, DIi, DTRk, XPJ, DTRk, DIi);

    // 6) dt = softplus(dt_lin + dtproj_b)
    softplus_kernel<<<dim3((Mm*DIi)/256, 2), 256>>>(dtproj_bf, dtproj_br);

    // 7) selective scan (both dirs), gated by silu(z)
    scan_kernel<<<dim3(DIi/32, Bb, 2), 512>>>(alog_f, dp_f, alog_r, dp_r);

    // 8) ysum = yg_f + reverse(yg_r)   (into g_dt region)
    combine_kernel<<<(Mm*DIi)/256, 256>>>();

    // 9) mamba_out = ysum @ outproj_w^T   (4096 x 1024 x 2048)
    sgemm_nt<<<dim3(Dd/128, Mm/128), 256>>>(p_dt, outproj_w, p_mout, Mm, Dd, DIi, DIi, DIi, Dd);

    // 10) residual2 = mamba_out + res1 (-> d_out second half); h2 = LN2(residual2)
    add_ln_kernel<<<Mm, 256>>>(p_mout, p_res1, ln2w, ln2b, res2_out, p_h2);

    // 11) gate = h2 @ gate_w^T (into g_xz), up = h2 @ up_w^T (into g_xc)
    sgemm_nt<<<dim3(Iff/128, Mm/128), 256>>>(p_h2, gate_w, p_xz, Mm, Iff, Dd, Dd, Dd, Iff);
    sgemm_nt<<<dim3(Iff/128, Mm/128), 256>>>(p_h2, up_w,   p_xc, Mm, Iff, Dd, Dd, Dd, Iff);

    // 12) up *= silu(gate)
    silumul_kernel<<<(Mm*Iff)/256, 256>>>();

    // 13) h = (silu(gate)*up) @ down_w^T  -> d_out first half  (4096 x 1024 x 4096)
    sgemm_nt<<<dim3(Dd/128, Mm/128), 256>>>(p_xc, down_w, out, Mm, Dd, Iff, Iff, Iff, Dd);
}

// round 11
// speedup vs baseline: 1.7518x; 1.7518x over previous
#include <cuda_runtime.h>
#include <math.h>

// ---------------- problem constants ----------------
#define Bb    2
#define Ll    2048
#define Dd    1024
#define DIi   2048
#define Nn    16
#define DCV   4
#define DTRk  64
#define Iff   4096
#define Mm    (Bb*Ll)          // 4096 tokens
#define XPJ   (DTRk + 2*Nn)    // 96
#define XZW   (2*DIi)          // 4096
#define EPSf  1e-5f

// ---------------- scratch (device globals; aliased across phases) ----------------
// g_xz : xz (inproj out)          -> later reused as gate pre-activation (M x I)
// g_xc : conv+silu x, f/r         -> later reused as up (M x I)
// g_dt : softplus(dt), f/r        -> later reused as ysum (M x DI)
// g_yg : gated scan output, f/r
__device__ float g_res1[(size_t)Mm*Dd];
__device__ float g_h1  [(size_t)Mm*Dd];
__device__ float g_mout[(size_t)Mm*Dd];
__device__ float g_h2  [(size_t)Mm*Dd];
__device__ float g_xz  [(size_t)Mm*XZW];
__device__ float g_xc  [2][(size_t)Mm*DIi];
__device__ float g_dt  [2][(size_t)Mm*DIi];
__device__ float g_yg  [2][(size_t)Mm*DIi];
__device__ float g_xdbl[2][(size_t)Mm*XPJ];

// ---------------- fused add + LayerNorm (row = token, D = 1024) ----------------
__global__ void add_ln_kernel(const float* __restrict__ a, const float* __restrict__ b,
                              const float* __restrict__ w, const float* __restrict__ bias,
                              float* __restrict__ sum_out, float* __restrict__ ln_out)
{
    const int row = blockIdx.x;
    const int tid = threadIdx.x;                  // 256 threads, 4 elems each
    const size_t base = (size_t)row * Dd;
    float4 va = ((const float4*)(a + base))[tid];
    float4 vb = ((const float4*)(b + base))[tid];
    float4 v  = make_float4(va.x+vb.x, va.y+vb.y, va.z+vb.z, va.w+vb.w);

    float s  = v.x + v.y + v.z + v.w;
    float sq = v.x*v.x + v.y*v.y + v.z*v.z + v.w*v.w;
    #pragma unroll
    for (int o = 16; o > 0; o >>= 1) {
        s  += __shfl_xor_sync(0xffffffffu, s,  o);
        sq += __shfl_xor_sync(0xffffffffu, sq, o);
    }
    __shared__ float ssum[8], ssq[8];
    const int wid = tid >> 5, lane = tid & 31;
    if (lane == 0) { ssum[wid] = s; ssq[wid] = sq; }
    __syncthreads();
    if (tid == 0) {
        float S = 0.f, Q = 0.f;
        #pragma unroll
        for (int i = 0; i < 8; ++i) { S += ssum[i]; Q += ssq[i]; }
        float mean = S * (1.0f/Dd);
        float var  = Q * (1.0f/Dd) - mean*mean;
        ssum[0] = mean;
        ssq[0]  = rsqrtf(var + EPSf);
    }
    __syncthreads();
    const float mean = ssum[0], rstd = ssq[0];

    if (sum_out) ((float4*)(sum_out + base))[tid] = v;
    float4 w4 = ((const float4*)w)[tid];
    float4 b4 = ((const float4*)bias)[tid];
    float4 o;
    o.x = (v.x - mean) * rstd * w4.x + b4.x;
    o.y = (v.y - mean) * rstd * w4.y + b4.y;
    o.z = (v.z - mean) * rstd * w4.z + b4.z;
    o.w = (v.w - mean) * rstd * w4.w + b4.w;
    ((float4*)(ln_out + base))[tid] = o;
}

// ---------------- TF32 tensor-core GEMM  C[m,n] = sum_k A[m,k]*B[n,k]  (NT) ----------------
// 128x128 CTA tile, BK=16, 256 threads = 8 warps, warp tile 64x32, m16n8k8 tf32 mma.sync,
// double-buffered smem with row pitch 20 (conflict-free fragment LDS).
// Requires: M % 128 == 0, K % 16 == 0, lda/ldb/ldc % 4 == 0, N even.

__device__ __forceinline__ unsigned f2tf(float f) {
    unsigned u;
    asm("cvt.rna.tf32.f32 %0, %1;" : "=r"(u) : "f"(f));
    return u;
}

#define MMA_TF32(d, a, b) \
    asm volatile("mma.sync.aligned.m16n8k8.row.col.f32.tf32.tf32.f32 " \
                 "{%0,%1,%2,%3}, {%4,%5,%6,%7}, {%8,%9}, {%0,%1,%2,%3};" \
                 : "+f"(d[0]), "+f"(d[1]), "+f"(d[2]), "+f"(d[3]) \
                 : "r"(a[0]), "r"(a[1]), "r"(a[2]), "r"(a[3]), "r"(b[0]), "r"(b[1]))

__global__ __launch_bounds__(256, 2)
void mma_tf32_nt(const float* __restrict__ A, const float* __restrict__ Bm,
                 float* __restrict__ C, int M, int N, int K,
                 int lda, int ldb, int ldc)
{
    __shared__ __align__(16) unsigned As[2][128][20];
    __shared__ __align__(16) unsigned Bs[2][128][20];

    const int bm = blockIdx.y * 128;
    const int bn = blockIdx.x * 128;
    const int tid = threadIdx.x;

    const int warp  = tid >> 5;
    const int lane  = tid & 31;
    const int gid   = lane >> 2;      // 0..7
    const int tig   = lane & 3;       // 0..3
    const int warpM = (warp & 1) * 64;
    const int warpN = (warp >> 1) * 32;

    // global->smem: each thread owns one half-row (8 floats) of the A and B tiles
    const int lrow = tid >> 1;             // 0..127
    const int lcol = (tid & 1) * 8;        // 0 or 8
    const float* Ag = A  + (size_t)(bm + lrow) * lda + lcol;   // M%128==0 -> valid
    const float* Bg = Bm + (size_t)(bn + lrow) * ldb + lcol;
    const bool  bok = (bn + lrow) < N;

    float acc[4][4][4];
    #pragma unroll
    for (int mi = 0; mi < 4; ++mi)
        #pragma unroll
        for (int ni = 0; ni < 4; ++ni)
            #pragma unroll
            for (int r = 0; r < 4; ++r) acc[mi][ni][r] = 0.f;

    const int nk = K >> 4;

    // prologue: stage 0
    {
        float4 a0 = *(const float4*)(Ag);
        float4 a1 = *(const float4*)(Ag + 4);
        float4 b0 = bok ? *(const float4*)(Bg)     : make_float4(0,0,0,0);
        float4 b1 = bok ? *(const float4*)(Bg + 4) : make_float4(0,0,0,0);
        uint4 ua0 = make_uint4(f2tf(a0.x), f2tf(a0.y), f2tf(a0.z), f2tf(a0.w));
        uint4 ua1 = make_uint4(f2tf(a1.x), f2tf(a1.y), f2tf(a1.z), f2tf(a1.w));
        uint4 ub0 = make_uint4(f2tf(b0.x), f2tf(b0.y), f2tf(b0.z), f2tf(b0.w));
        uint4 ub1 = make_uint4(f2tf(b1.x), f2tf(b1.y), f2tf(b1.z), f2tf(b1.w));
        *(uint4*)&As[0][lrow][lcol]     = ua0;
        *(uint4*)&As[0][lrow][lcol + 4] = ua1;
        *(uint4*)&Bs[0][lrow][lcol]     = ub0;
        *(uint4*)&Bs[0][lrow][lcol + 4] = ub1;
    }
    __syncthreads();

    for (int kt = 0; kt < nk; ++kt) {
        const int s = kt & 1;
        const bool pre = (kt + 1) < nk;
        float4 pa0, pa1, pb0, pb1;
        if (pre) {
            const int koff = (kt + 1) << 4;
            pa0 = *(const float4*)(Ag + koff);
            pa1 = *(const float4*)(Ag + koff + 4);
            pb0 = bok ? *(const float4*)(Bg + koff)     : make_float4(0,0,0,0);
            pb1 = bok ? *(const float4*)(Bg + koff + 4) : make_float4(0,0,0,0);
        }

        #pragma unroll
        for (int ks = 0; ks < 16; ks += 8) {
            unsigned af[4][4], bf[4][2];
            #pragma unroll
            for (int mi = 0; mi < 4; ++mi) {
                const int r = warpM + mi * 16 + gid;
                af[mi][0] = As[s][r    ][ks + tig];
                af[mi][1] = As[s][r + 8][ks + tig];
                af[mi][2] = As[s][r    ][ks + tig + 4];
                af[mi][3] = As[s][r + 8][ks + tig + 4];
            }
            #pragma unroll
            for (int ni = 0; ni < 4; ++ni) {
                const int c = warpN + ni * 8 + gid;
                bf[ni][0] = Bs[s][c][ks + tig];
                bf[ni][1] = Bs[s][c][ks + tig + 4];
            }
            #pragma unroll
            for (int mi = 0; mi < 4; ++mi)
                #pragma unroll
                for (int ni = 0; ni < 4; ++ni)
                    MMA_TF32(acc[mi][ni], af[mi], bf[ni]);
        }

        if (pre) {
            const int t = s ^ 1;
            uint4 ua0 = make_uint4(f2tf(pa0.x), f2tf(pa0.y), f2tf(pa0.z), f2tf(pa0.w));
            uint4 ua1 = make_uint4(f2tf(pa1.x), f2tf(pa1.y), f2tf(pa1.z), f2tf(pa1.w));
            uint4 ub0 = make_uint4(f2tf(pb0.x), f2tf(pb0.y), f2tf(pb0.z), f2tf(pb0.w));
            uint4 ub1 = make_uint4(f2tf(pb1.x), f2tf(pb1.y), f2tf(pb1.z), f2tf(pb1.w));
            *(uint4*)&As[t][lrow][lcol]     = ua0;
            *(uint4*)&As[t][lrow][lcol + 4] = ua1;
            *(uint4*)&Bs[t][lrow][lcol]     = ub0;
            *(uint4*)&Bs[t][lrow][lcol + 4] = ub1;
        }
        __syncthreads();
    }

    // epilogue: float2 stores (N is always even in this problem)
    #pragma unroll
    for (int mi = 0; mi < 4; ++mi) {
        const int r = bm + warpM + mi * 16 + gid;
        #pragma unroll
        for (int ni = 0; ni < 4; ++ni) {
            const int c = bn + warpN + ni * 8 + tig * 2;
            if (c < N) {
                float2 lo = make_float2(acc[mi][ni][0], acc[mi][ni][1]);
                float2 hi = make_float2(acc[mi][ni][2], acc[mi][ni][3]);
                *(float2*)&C[(size_t)r * ldc + c]       = lo;
                *(float2*)&C[(size_t)(r + 8) * ldc + c] = hi;
            }
        }
    }
}

// ---------------- depthwise causal conv (k=4) + SiLU, both directions ----------------
__global__ void conv_silu_kernel(const float* __restrict__ wf, const float* __restrict__ bf,
                                 const float* __restrict__ wr, const float* __restrict__ br)
{
    const int idx = blockIdx.x * blockDim.x + threadIdx.x;
    if (idx >= Mm * DIi) return;
    const int dir = blockIdx.y;
    const int d = idx % DIi;
    const int t = idx / DIi;
    const int b = t / Ll, l = t % Ll;
    const float* w  = dir ? wr : wf;
    const float* bi = dir ? br : bf;
    float acc = bi[d];
    #pragma unroll
    for (int k = 0; k < DCV; ++k) {
        const int lk = l - (DCV-1) + k;
        if (lk >= 0) {
            const int lsrc = dir ? (Ll - 1 - lk) : lk;
            acc = fmaf(g_xz[((size_t)b*Ll + lsrc) * XZW + d], w[d*DCV + k], acc);
        }
    }
    g_xc[dir][idx] = acc / (1.f + __expf(-acc));   // SiLU
}

// ---------------- softplus(dt_lin + dtproj_b), in place ----------------
__global__ void softplus_kernel(const float* __restrict__ bf, const float* __restrict__ br)
{
    const size_t idx = (size_t)blockIdx.x * blockDim.x + threadIdx.x;
    if (idx >= (size_t)Mm * DIi) return;
    const int dir = blockIdx.y;
    const int d = (int)(idx % DIi);
    const float x = g_dt[dir][idx] + (dir ? br[d] : bf[d]);
    g_dt[dir][idx] = (x > 20.f) ? x : log1pf(__expf(x));
}

// ---------------- selective-state scan: thread per (b,d,n), 16-lane reduce ----------------
__global__ void scan_kernel(const float* __restrict__ alog_f, const float* __restrict__ dp_f,
                            const float* __restrict__ alog_r, const float* __restrict__ dp_r)
{
    const int dir = blockIdx.z;
    const int b   = blockIdx.y;
    const int d   = blockIdx.x * 32 + (threadIdx.x >> 4);
    const int n   = threadIdx.x & 15;

    const float* alog = dir ? alog_r : alog_f;
    const float* dp   = dir ? dp_r   : dp_f;
    const float A  = -expf(alog[d * Nn + n]);
    const float Dv = dp[d];
    const float* dt = g_dt[dir];
    const float* xc = g_xc[dir];
    const float* xd = g_xdbl[dir];
    float* yg = g_yg[dir];

    float s = 0.f;
    for (int l = 0; l < Ll; ++l) {
        const size_t t = (size_t)b * Ll + l;
        const float dtv = dt[t * DIi + d];
        const float xv  = xc[t * DIi + d];
        const float Bn  = xd[t * XPJ + DTRk + n];
        const float Cn  = xd[t * XPJ + DTRk + Nn + n];
        const float dA  = __expf(dtv * A);
        s = fmaf(s, dA, dtv * xv * Bn);
        float p = s * Cn;
        p += __shfl_xor_sync(0xffffffffu, p, 8);
        p += __shfl_xor_sync(0xffffffffu, p, 4);
        p += __shfl_xor_sync(0xffffffffu, p, 2);
        p += __shfl_xor_sync(0xffffffffu, p, 1);
        if (n == 0) {
            float y = p + xv * Dv;
            const int lz = dir ? (Ll - 1 - l) : l;                 // z in original order
            const float zv = g_xz[((size_t)b*Ll + lz) * XZW + DIi + d];
            y *= zv / (1.f + __expf(-zv));                          // * silu(z)
            yg[t * DIi + d] = y;
        }
    }
}

// ---------------- ysum[b,l,d] = yg_f[b,l,d] + yg_r[b,L-1-l,d]  (into g_dt[0]) ----------------
__global__ void combine_kernel()
{
    const size_t idx = (size_t)blockIdx.x * blockDim.x + threadIdx.x;
    if (idx >= (size_t)Mm * DIi) return;
    const int d = (int)(idx % DIi);
    const int t = (int)(idx / DIi);
    const int b = t / Ll, l = t % Ll;
    ((float*)g_dt)[idx] = g_yg[0][idx] + g_yg[1][((size_t)b*Ll + (Ll-1-l)) * DIi + d];
}

// ---------------- up = silu(gate) * up  (gate in g_xz, up in g_xc, flat M*I) ----------------
__global__ void silumul_kernel()
{
    const size_t idx = (size_t)blockIdx.x * blockDim.x + threadIdx.x;
    if (idx >= (size_t)Mm * Iff) return;
    const float g = g_xz[idx];
    ((float*)g_xc)[idx] = ((float*)g_xc)[idx] * g / (1.f + __expf(-g));
}

// ---------------- host ----------------
extern "C" void kernel_launch(void* const* d_in, const int* in_sizes, int n_in,
                              void* d_out, int out_size)
{
    const float* hs       = (const float*)d_in[0];
    const float* res      = (const float*)d_in[1];
    const float* inproj_w = (const float*)d_in[2];
    const float* outproj_w= (const float*)d_in[3];
    const float* conv_w_f = (const float*)d_in[4];
    const float* conv_b_f = (const float*)d_in[5];
    const float* xproj_w_f= (const float*)d_in[6];
    const float* dtproj_wf= (const float*)d_in[7];
    const float* dtproj_bf= (const float*)d_in[8];
    const float* alog_f   = (const float*)d_in[9];
    const float* dp_f     = (const float*)d_in[10];
    const float* conv_w_r = (const float*)d_in[11];
    const float* conv_b_r = (const float*)d_in[12];
    const float* xproj_w_r= (const float*)d_in[13];
    const float* dtproj_wr= (const float*)d_in[14];
    const float* dtproj_br= (const float*)d_in[15];
    const float* alog_r   = (const float*)d_in[16];
    const float* dp_r     = (const float*)d_in[17];
    const float* ln1w = (const float*)d_in[18];
    const float* ln1b = (const float*)d_in[19];
    const float* ln2w = (const float*)d_in[20];
    const float* ln2b = (const float*)d_in[21];
    const float* gate_w = (const float*)d_in[22];
    const float* up_w   = (const float*)d_in[23];
    const float* down_w = (const float*)d_in[24];

    float* out = (float*)d_out;
    float* res2_out = (out_size >= 2 * Mm * Dd) ? (out + (size_t)Mm * Dd) : nullptr;

    float *p_res1, *p_h1, *p_mout, *p_h2, *p_xz, *p_xc, *p_dt, *p_xdbl;
    cudaGetSymbolAddress((void**)&p_res1, g_res1);
    cudaGetSymbolAddress((void**)&p_h1,   g_h1);
    cudaGetSymbolAddress((void**)&p_mout, g_mout);
    cudaGetSymbolAddress((void**)&p_h2,   g_h2);
    cudaGetSymbolAddress((void**)&p_xz,   g_xz);
    cudaGetSymbolAddress((void**)&p_xc,   g_xc);
    cudaGetSymbolAddress((void**)&p_dt,   g_dt);
    cudaGetSymbolAddress((void**)&p_xdbl, g_xdbl);
    float* p_xcf   = p_xc;
    float* p_xcr   = p_xc + (size_t)Mm * DIi;
    float* p_dtf   = p_dt;
    float* p_dtr   = p_dt + (size_t)Mm * DIi;
    float* p_xdblf = p_xdbl;
    float* p_xdblr = p_xdbl + (size_t)Mm * XPJ;

    // 1) res1 = hs + residual; h1 = LN1(res1)
    add_ln_kernel<<<Mm, 256>>>(hs, res, ln1w, ln1b, p_res1, p_h1);

    // 2) xz = h1 @ inproj_w^T     (4096 x 4096 x 1024)
    mma_tf32_nt<<<dim3(XZW/128, Mm/128), 256>>>(p_h1, inproj_w, p_xz, Mm, XZW, Dd, Dd, Dd, XZW);

    // 3) conv + silu (both directions; reverse stored in reversed-l domain)
    conv_silu_kernel<<<dim3((Mm*DIi)/256, 2), 256>>>(conv_w_f, conv_b_f, conv_w_r, conv_b_r);

    // 4) x_dbl = x @ xproj_w^T    (4096 x 96 x 2048) per dir
    mma_tf32_nt<<<dim3(1, Mm/128), 256>>>(p_xcf, xproj_w_f, p_xdblf, Mm, XPJ, DIi, DIi, DIi, XPJ);
    mma_tf32_nt<<<dim3(1, Mm/128), 256>>>(p_xcr, xproj_w_r, p_xdblr, Mm, XPJ, DIi, DIi, DIi, XPJ);

    // 5) dt_lin = dt_part @ dtproj_w^T   (4096 x 2048 x 64) per dir
    mma_tf32_nt<<<dim3(DIi/128, Mm/128), 256>>>(p_xdblf, dtproj_wf, p_dtf, Mm, DIi, DTRk, XPJ, DTRk, DIi);
    mma_tf32_nt<<<dim3(DIi/128, Mm/128), 256>>>(p_xdblr, dtproj_wr, p_dtr, Mm, DIi, DTRk, XPJ, DTRk, DIi);

    // 6) dt = softplus(dt_lin + dtproj_b)
    softplus_kernel<<<dim3((Mm*DIi)/256, 2), 256>>>(dtproj_bf, dtproj_br);

    // 7) selective scan (both dirs), gated by silu(z)
    scan_kernel<<<dim3(DIi/32, Bb, 2), 512>>>(alog_f, dp_f, alog_r, dp_r);

    // 8) ysum = yg_f + reverse(yg_r)   (into g_dt region)
    combine_kernel<<<(Mm*DIi)/256, 256>>>();

    // 9) mamba_out = ysum @ outproj_w^T   (4096 x 1024 x 2048)
    mma_tf32_nt<<<dim3(Dd/128, Mm/128), 256>>>(p_dt, outproj_w, p_mout, Mm, Dd, DIi, DIi, DIi, Dd);

    // 10) residual2 = mamba_out + res1; h2 = LN2(residual2)
    add_ln_kernel<<<Mm, 256>>>(p_mout, p_res1, ln2w, ln2b, res2_out, p_h2);

    // 11) gate = h2 @ gate_w^T (into g_xz), up = h2 @ up_w^T (into g_xc)
    mma_tf32_nt<<<dim3(Iff/128, Mm/128), 256>>>(p_h2, gate_w, p_xz, Mm, Iff, Dd, Dd, Dd, Iff);
    mma_tf32_nt<<<dim3(Iff/128, Mm/128), 256>>>(p_h2, up_w,   p_xc, Mm, Iff, Dd, Dd, Dd, Iff);

    // 12) up *= silu(gate)
    silumul_kernel<<<(Mm*Iff)/256, 256>>>();

    // 13) h = (silu(gate)*up) @ down_w^T  -> d_out first half  (4096 x 1024 x 4096)
    mma_tf32_nt<<<dim3(Dd/128, Mm/128), 256>>>(p_xc, down_w, out, Mm, Dd, Iff, Iff, Iff, Dd);
}

// round 12
// speedup vs baseline: 1.7526x; 1.0005x over previous
#include <cuda_runtime.h>
#include <math.h>

// ---------------- problem constants ----------------
#define Bb    2
#define Ll    2048
#define Dd    1024
#define DIi   2048
#define Nn    16
#define DCV   4
#define DTRk  64
#define Iff   4096
#define Mm    (Bb*Ll)          // 4096 tokens
#define XPJ   (DTRk + 2*Nn)    // 96
#define XZW   (2*DIi)          // 4096
#define EPSf  1e-5f

// ---------------- scratch (device globals; aliased across phases) ----------------
// g_xz : xz (inproj out)          -> later reused as gate pre-activation (M x I)
// g_xc : conv+silu x, f/r         -> later reused as up (M x I)
// g_dt : softplus(dt), f/r        -> later reused as ysum (M x DI)
// g_yg : gated scan output, f/r
__device__ float g_res1[(size_t)Mm*Dd];
__device__ float g_h1  [(size_t)Mm*Dd];
__device__ float g_mout[(size_t)Mm*Dd];
__device__ float g_h2  [(size_t)Mm*Dd];
__device__ float g_xz  [(size_t)Mm*XZW];
__device__ float g_xc  [2][(size_t)Mm*DIi];
__device__ float g_dt  [2][(size_t)Mm*DIi];
__device__ float g_yg  [2][(size_t)Mm*DIi];
__device__ float g_xdbl[2][(size_t)Mm*XPJ];

// ---------------- fused add + LayerNorm (row = token, D = 1024) ----------------
__global__ void add_ln_kernel(const float* __restrict__ a, const float* __restrict__ b,
                              const float* __restrict__ w, const float* __restrict__ bias,
                              float* __restrict__ sum_out, float* __restrict__ ln_out)
{
    const int row = blockIdx.x;
    const int tid = threadIdx.x;                  // 256 threads, 4 elems each
    const size_t base = (size_t)row * Dd;
    float4 va = ((const float4*)(a + base))[tid];
    float4 vb = ((const float4*)(b + base))[tid];
    float4 v  = make_float4(va.x+vb.x, va.y+vb.y, va.z+vb.z, va.w+vb.w);

    float s  = v.x + v.y + v.z + v.w;
    float sq = v.x*v.x + v.y*v.y + v.z*v.z + v.w*v.w;
    #pragma unroll
    for (int o = 16; o > 0; o >>= 1) {
        s  += __shfl_xor_sync(0xffffffffu, s,  o);
        sq += __shfl_xor_sync(0xffffffffu, sq, o);
    }
    __shared__ float ssum[8], ssq[8];
    const int wid = tid >> 5, lane = tid & 31;
    if (lane == 0) { ssum[wid] = s; ssq[wid] = sq; }
    __syncthreads();
    if (tid == 0) {
        float S = 0.f, Q = 0.f;
        #pragma unroll
        for (int i = 0; i < 8; ++i) { S += ssum[i]; Q += ssq[i]; }
        float mean = S * (1.0f/Dd);
        float var  = Q * (1.0f/Dd) - mean*mean;
        ssum[0] = mean;
        ssq[0]  = rsqrtf(var + EPSf);
    }
    __syncthreads();
    const float mean = ssum[0], rstd = ssq[0];

    if (sum_out) ((float4*)(sum_out + base))[tid] = v;
    float4 w4 = ((const float4*)w)[tid];
    float4 b4 = ((const float4*)bias)[tid];
    float4 o;
    o.x = (v.x - mean) * rstd * w4.x + b4.x;
    o.y = (v.y - mean) * rstd * w4.y + b4.y;
    o.z = (v.z - mean) * rstd * w4.z + b4.z;
    o.w = (v.w - mean) * rstd * w4.w + b4.w;
    ((float4*)(ln_out + base))[tid] = o;
}

// ---------------- TF32 tensor-core GEMM  C[m,n] = sum_k A[m,k]*B[n,k]  (NT) ----------------
// 128x128 CTA tile, BK=16, 256 threads = 8 warps, warp tile 64x32, m16n8k8 tf32 mma.sync,
// double-buffered smem with row pitch 20 (conflict-free fragment LDS).
// Requires: M % 128 == 0, K % 16 == 0, lda/ldb/ldc % 4 == 0, N even.

__device__ __forceinline__ unsigned f2tf(float f) {
    unsigned u;
    asm("cvt.rna.tf32.f32 %0, %1;" : "=r"(u) : "f"(f));
    return u;
}

#define MMA_TF32(d, a, b) \
    asm volatile("mma.sync.aligned.m16n8k8.row.col.f32.tf32.tf32.f32 " \
                 "{%0,%1,%2,%3}, {%4,%5,%6,%7}, {%8,%9}, {%0,%1,%2,%3};" \
                 : "+f"(d[0]), "+f"(d[1]), "+f"(d[2]), "+f"(d[3]) \
                 : "r"(a[0]), "r"(a[1]), "r"(a[2]), "r"(a[3]), "r"(b[0]), "r"(b[1]))

__global__ __launch_bounds__(256, 2)
void mma_tf32_nt(const float* __restrict__ A, const float* __restrict__ Bm,
                 float* __restrict__ C, int M, int N, int K,
                 int lda, int ldb, int ldc)
{
    __shared__ __align__(16) unsigned As[2][128][20];
    __shared__ __align__(16) unsigned Bs[2][128][20];

    const int bm = blockIdx.y * 128;
    const int bn = blockIdx.x * 128;
    const int tid = threadIdx.x;

    const int warp  = tid >> 5;
    const int lane  = tid & 31;
    const int gid   = lane >> 2;      // 0..7
    const int tig   = lane & 3;       // 0..3
    const int warpM = (warp & 1) * 64;
    const int warpN = (warp >> 1) * 32;

    // global->smem: each thread owns one half-row (8 floats) of the A and B tiles
    const int lrow = tid >> 1;             // 0..127
    const int lcol = (tid & 1) * 8;        // 0 or 8
    const float* Ag = A  + (size_t)(bm + lrow) * lda + lcol;   // M%128==0 -> valid
    const float* Bg = Bm + (size_t)(bn + lrow) * ldb + lcol;
    const bool  bok = (bn + lrow) < N;

    float acc[4][4][4];
    #pragma unroll
    for (int mi = 0; mi < 4; ++mi)
        #pragma unroll
        for (int ni = 0; ni < 4; ++ni)
            #pragma unroll
            for (int r = 0; r < 4; ++r) acc[mi][ni][r] = 0.f;

    const int nk = K >> 4;

    // prologue: stage 0
    {
        float4 a0 = *(const float4*)(Ag);
        float4 a1 = *(const float4*)(Ag + 4);
        float4 b0 = bok ? *(const float4*)(Bg)     : make_float4(0,0,0,0);
        float4 b1 = bok ? *(const float4*)(Bg + 4) : make_float4(0,0,0,0);
        uint4 ua0 = make_uint4(f2tf(a0.x), f2tf(a0.y), f2tf(a0.z), f2tf(a0.w));
        uint4 ua1 = make_uint4(f2tf(a1.x), f2tf(a1.y), f2tf(a1.z), f2tf(a1.w));
        uint4 ub0 = make_uint4(f2tf(b0.x), f2tf(b0.y), f2tf(b0.z), f2tf(b0.w));
        uint4 ub1 = make_uint4(f2tf(b1.x), f2tf(b1.y), f2tf(b1.z), f2tf(b1.w));
        *(uint4*)&As[0][lrow][lcol]     = ua0;
        *(uint4*)&As[0][lrow][lcol + 4] = ua1;
        *(uint4*)&Bs[0][lrow][lcol]     = ub0;
        *(uint4*)&Bs[0][lrow][lcol + 4] = ub1;
    }
    __syncthreads();

    for (int kt = 0; kt < nk; ++kt) {
        const int s = kt & 1;
        const bool pre = (kt + 1) < nk;
        float4 pa0, pa1, pb0, pb1;
        if (pre) {
            const int koff = (kt + 1) << 4;
            pa0 = *(const float4*)(Ag + koff);
            pa1 = *(const float4*)(Ag + koff + 4);
            pb0 = bok ? *(const float4*)(Bg + koff)     : make_float4(0,0,0,0);
            pb1 = bok ? *(const float4*)(Bg + koff + 4) : make_float4(0,0,0,0);
        }

        #pragma unroll
        for (int ks = 0; ks < 16; ks += 8) {
            unsigned af[4][4], bf[4][2];
            #pragma unroll
            for (int mi = 0; mi < 4; ++mi) {
                const int r = warpM + mi * 16 + gid;
                af[mi][0] = As[s][r    ][ks + tig];
                af[mi][1] = As[s][r + 8][ks + tig];
                af[mi][2] = As[s][r    ][ks + tig + 4];
                af[mi][3] = As[s][r + 8][ks + tig + 4];
            }
            #pragma unroll
            for (int ni = 0; ni < 4; ++ni) {
                const int c = warpN + ni * 8 + gid;
                bf[ni][0] = Bs[s][c][ks + tig];
                bf[ni][1] = Bs[s][c][ks + tig + 4];
            }
            #pragma unroll
            for (int mi = 0; mi < 4; ++mi)
                #pragma unroll
                for (int ni = 0; ni < 4; ++ni)
                    MMA_TF32(acc[mi][ni], af[mi], bf[ni]);
        }

        if (pre) {
            const int t = s ^ 1;
            uint4 ua0 = make_uint4(f2tf(pa0.x), f2tf(pa0.y), f2tf(pa0.z), f2tf(pa0.w));
            uint4 ua1 = make_uint4(f2tf(pa1.x), f2tf(pa1.y), f2tf(pa1.z), f2tf(pa1.w));
            uint4 ub0 = make_uint4(f2tf(pb0.x), f2tf(pb0.y), f2tf(pb0.z), f2tf(pb0.w));
            uint4 ub1 = make_uint4(f2tf(pb1.x), f2tf(pb1.y), f2tf(pb1.z), f2tf(pb1.w));
            *(uint4*)&As[t][lrow][lcol]     = ua0;
            *(uint4*)&As[t][lrow][lcol + 4] = ua1;
            *(uint4*)&Bs[t][lrow][lcol]     = ub0;
            *(uint4*)&Bs[t][lrow][lcol + 4] = ub1;
        }
        __syncthreads();
    }

    // epilogue: float2 stores (N is always even in this problem)
    #pragma unroll
    for (int mi = 0; mi < 4; ++mi) {
        const int r = bm + warpM + mi * 16 + gid;
        #pragma unroll
        for (int ni = 0; ni < 4; ++ni) {
            const int c = bn + warpN + ni * 8 + tig * 2;
            if (c < N) {
                float2 lo = make_float2(acc[mi][ni][0], acc[mi][ni][1]);
                float2 hi = make_float2(acc[mi][ni][2], acc[mi][ni][3]);
                *(float2*)&C[(size_t)r * ldc + c]       = lo;
                *(float2*)&C[(size_t)(r + 8) * ldc + c] = hi;
            }
        }
    }
}

// ---------------- depthwise causal conv (k=4) + SiLU, both directions ----------------
__global__ void conv_silu_kernel(const float* __restrict__ wf, const float* __restrict__ bf,
                                 const float* __restrict__ wr, const float* __restrict__ br)
{
    const int idx = blockIdx.x * blockDim.x + threadIdx.x;
    if (idx >= Mm * DIi) return;
    const int dir = blockIdx.y;
    const int d = idx % DIi;
    const int t = idx / DIi;
    const int b = t / Ll, l = t % Ll;
    const float* w  = dir ? wr : wf;
    const float* bi = dir ? br : bf;
    float acc = bi[d];
    #pragma unroll
    for (int k = 0; k < DCV; ++k) {
        const int lk = l - (DCV-1) + k;
        if (lk >= 0) {
            const int lsrc = dir ? (Ll - 1 - lk) : lk;
            acc = fmaf(g_xz[((size_t)b*Ll + lsrc) * XZW + d], w[d*DCV + k], acc);
        }
    }
    g_xc[dir][idx] = acc / (1.f + __expf(-acc));   // SiLU
}

// ---------------- softplus(dt_lin + dtproj_b), in place ----------------
__global__ void softplus_kernel(const float* __restrict__ bf, const float* __restrict__ br)
{
    const size_t idx = (size_t)blockIdx.x * blockDim.x + threadIdx.x;
    if (idx >= (size_t)Mm * DIi) return;
    const int dir = blockIdx.y;
    const int d = (int)(idx % DIi);
    const float x = g_dt[dir][idx] + (dir ? br[d] : bf[d]);
    g_dt[dir][idx] = (x > 20.f) ? x : log1pf(__expf(x));
}

// ---------------- selective-state scan: thread per (b,d,n), 16-lane reduce ----------------
__global__ void scan_kernel(const float* __restrict__ alog_f, const float* __restrict__ dp_f,
                            const float* __restrict__ alog_r, const float* __restrict__ dp_r)
{
    const int dir = blockIdx.z;
    const int b   = blockIdx.y;
    const int d   = blockIdx.x * 32 + (threadIdx.x >> 4);
    const int n   = threadIdx.x & 15;

    const float* alog = dir ? alog_r : alog_f;
    const float* dp   = dir ? dp_r   : dp_f;
    const float A  = -expf(alog[d * Nn + n]);
    const float Dv = dp[d];
    const float* dt = g_dt[dir];
    const float* xc = g_xc[dir];
    const float* xd = g_xdbl[dir];
    float* yg = g_yg[dir];

    float s = 0.f;
    for (int l = 0; l < Ll; ++l) {
        const size_t t = (size_t)b * Ll + l;
        const float dtv = dt[t * DIi + d];
        const float xv  = xc[t * DIi + d];
        const float Bn  = xd[t * XPJ + DTRk + n];
        const float Cn  = xd[t * XPJ + DTRk + Nn + n];
        const float dA  = __expf(dtv * A);
        s = fmaf(s, dA, dtv * xv * Bn);
        float p = s * Cn;
        p += __shfl_xor_sync(0xffffffffu, p, 8);
        p += __shfl_xor_sync(0xffffffffu, p, 4);
        p += __shfl_xor_sync(0xffffffffu, p, 2);
        p += __shfl_xor_sync(0xffffffffu, p, 1);
        if (n == 0) {
            float y = p + xv * Dv;
            const int lz = dir ? (Ll - 1 - l) : l;                 // z in original order
            const float zv = g_xz[((size_t)b*Ll + lz) * XZW + DIi + d];
            y *= zv / (1.f + __expf(-zv));                          // * silu(z)
            yg[t * DIi + d] = y;
        }
    }
}

// ---------------- ysum[b,l,d] = yg_f[b,l,d] + yg_r[b,L-1-l,d]  (into g_dt[0]) ----------------
__global__ void combine_kernel()
{
    const size_t idx = (size_t)blockIdx.x * blockDim.x + threadIdx.x;
    if (idx >= (size_t)Mm * DIi) return;
    const int d = (int)(idx % DIi);
    const int t = (int)(idx / DIi);
    const int b = t / Ll, l = t % Ll;
    ((float*)g_dt)[idx] = g_yg[0][idx] + g_yg[1][((size_t)b*Ll + (Ll-1-l)) * DIi + d];
}

// ---------------- up = silu(gate) * up  (gate in g_xz, up in g_xc, flat M*I) ----------------
__global__ void silumul_kernel()
{
    const size_t idx = (size_t)blockIdx.x * blockDim.x + threadIdx.x;
    if (idx >= (size_t)Mm * Iff) return;
    const float g = g_xz[idx];
    ((float*)g_xc)[idx] = ((float*)g_xc)[idx] * g / (1.f + __expf(-g));
}

// ---------------- host ----------------
extern "C" void kernel_launch(void* const* d_in, const int* in_sizes, int n_in,
                              void* d_out, int out_size)
{
    const float* hs       = (const float*)d_in[0];
    const float* res      = (const float*)d_in[1];
    const float* inproj_w = (const float*)d_in[2];
    const float* outproj_w= (const float*)d_in[3];
    const float* conv_w_f = (const float*)d_in[4];
    const float* conv_b_f = (const float*)d_in[5];
    const float* xproj_w_f= (const float*)d_in[6];
    const float* dtproj_wf= (const float*)d_in[7];
    const float* dtproj_bf= (const float*)d_in[8];
    const float* alog_f   = (const float*)d_in[9];
    const float* dp_f     = (const float*)d_in[10];
    const float* conv_w_r = (const float*)d_in[11];
    const float* conv_b_r = (const float*)d_in[12];
    const float* xproj_w_r= (const float*)d_in[13];
    const float* dtproj_wr= (const float*)d_in[14];
    const float* dtproj_br= (const float*)d_in[15];
    const float* alog_r   = (const float*)d_in[16];
    const float* dp_r     = (const float*)d_in[17];
    const float* ln1w = (const float*)d_in[18];
    const float* ln1b = (const float*)d_in[19];
    const float* ln2w = (const float*)d_in[20];
    const float* ln2b = (const float*)d_in[21];
    const float* gate_w = (const float*)d_in[22];
    const float* up_w   = (const float*)d_in[23];
    const float* down_w = (const float*)d_in[24];

    float* out = (float*)d_out;
    float* res2_out = (out_size >= 2 * Mm * Dd) ? (out + (size_t)Mm * Dd) : nullptr;

    float *p_res1, *p_h1, *p_mout, *p_h2, *p_xz, *p_xc, *p_dt, *p_xdbl;
    cudaGetSymbolAddress((void**)&p_res1, g_res1);
    cudaGetSymbolAddress((void**)&p_h1,   g_h1);
    cudaGetSymbolAddress((void**)&p_mout, g_mout);
    cudaGetSymbolAddress((void**)&p_h2,   g_h2);
    cudaGetSymbolAddress((void**)&p_xz,   g_xz);
    cudaGetSymbolAddress((void**)&p_xc,   g_xc);
    cudaGetSymbolAddress((void**)&p_dt,   g_dt);
    cudaGetSymbolAddress((void**)&p_xdbl, g_xdbl);
    float* p_xcf   = p_xc;
    float* p_xcr   = p_xc + (size_t)Mm * DIi;
    float* p_dtf   = p_dt;
    float* p_dtr   = p_dt + (size_t)Mm * DIi;
    float* p_xdblf = p_xdbl;
    float* p_xdblr = p_xdbl + (size_t)Mm * XPJ;

    // 1) res1 = hs + residual; h1 = LN1(res1)
    add_ln_kernel<<<Mm, 256>>>(hs, res, ln1w, ln1b, p_res1, p_h1);

    // 2) xz = h1 @ inproj_w^T     (4096 x 4096 x 1024)
    mma_tf32_nt<<<dim3(XZW/128, Mm/128), 256>>>(p_h1, inproj_w, p_xz, Mm, XZW, Dd, Dd, Dd, XZW);

    // 3) conv + silu (both directions; reverse stored in reversed-l domain)
    conv_silu_kernel<<<dim3((Mm*DIi)/256, 2), 256>>>(conv_w_f, conv_b_f, conv_w_r, conv_b_r);

    // 4) x_dbl = x @ xproj_w^T    (4096 x 96 x 2048) per dir
    mma_tf32_nt<<<dim3(1, Mm/128), 256>>>(p_xcf, xproj_w_f, p_xdblf, Mm, XPJ, DIi, DIi, DIi, XPJ);
    mma_tf32_nt<<<dim3(1, Mm/128), 256>>>(p_xcr, xproj_w_r, p_xdblr, Mm, XPJ, DIi, DIi, DIi, XPJ);

    // 5) dt_lin = dt_part @ dtproj_w^T   (4096 x 2048 x 64) per dir
    mma_tf32_nt<<<dim3(DIi/128, Mm/128), 256>>>(p_xdblf, dtproj_wf, p_dtf, Mm, DIi, DTRk, XPJ, DTRk, DIi);
    mma_tf32_nt<<<dim3(DIi/128, Mm/128), 256>>>(p_xdblr, dtproj_wr, p_dtr, Mm, DIi, DTRk, XPJ, DTRk, DIi);

    // 6) dt = softplus(dt_lin + dtproj_b)
    softplus_kernel<<<dim3((Mm*DIi)/256, 2), 256>>>(dtproj_bf, dtproj_br);

    // 7) selective scan (both dirs), gated by silu(z)
    scan_kernel<<<dim3(DIi/32, Bb, 2), 512>>>(alog_f, dp_f, alog_r, dp_r);

    // 8) ysum = yg_f + reverse(yg_r)   (into g_dt region)
    combine_kernel<<<(Mm*DIi)/256, 256>>>();

    // 9) mamba_out = ysum @ outproj_w^T   (4096 x 1024 x 2048)
    mma_tf32_nt<<<dim3(Dd/128, Mm/128), 256>>>(p_dt, outproj_w, p_mout, Mm, Dd, DIi, DIi, DIi, Dd);

    // 10) residual2 = mamba_out + res1; h2 = LN2(residual2)
    add_ln_kernel<<<Mm, 256>>>(p_mout, p_res1, ln2w, ln2b, res2_out, p_h2);

    // 11) gate = h2 @ gate_w^T (into g_xz), up = h2 @ up_w^T (into g_xc)
    mma_tf32_nt<<<dim3(Iff/128, Mm/128), 256>>>(p_h2, gate_w, p_xz, Mm, Iff, Dd, Dd, Dd, Iff);
    mma_tf32_nt<<<dim3(Iff/128, Mm/128), 256>>>(p_h2, up_w,   p_xc, Mm, Iff, Dd, Dd, Dd, Iff);

    // 12) up *= silu(gate)
    silumul_kernel<<<(Mm*Iff)/256, 256>>>();

    // 13) h = (silu(gate)*up) @ down_w^T  -> d_out first half  (4096 x 1024 x 4096)
    mma_tf32_nt<<<dim3(Dd/128, Mm/128), 256>>>(p_xc, down_w, out, Mm, Dd, Iff, Iff, Iff, Dd);
}